// round 1
// baseline (speedup 1.0000x reference)
#include <cuda_runtime.h>
#include <cuda_bf16.h>
#include <cstdint>

#define EE    256
#define HH    4
#define DH    64
#define BB    8
#define CC    32
#define RR    255
#define SS    256
#define HID   1024
#define NBC   (BB*CC)      // 256 (b,c) pairs == tokens
#define LN_EPS 1e-5f

// ---------------- device scratch (no allocation allowed) ----------------
__device__ float g_u[HH*EE];        // scale * W_k[h]^T q0   (score projection)
__device__ float g_cb[HH];          // scale * q0[h] . b_k[h]
__device__ float g_bias2[EE];       // W_out @ b_v + b_out
__device__ float g_M2T[HID*EE];     // M2T[j][f] = sum_d W_out[f, h*DH+d]*W_v[h*DH+d, e], j=h*EE+e
__device__ float g_xbar[NBC*HID];   // per (b,c): [h*EE+e] attn-weighted x rows
__device__ float g_ln[NBC*EE];      // layernorm output per token

// ---------------- kernel 1: tiny precompute ----------------
__global__ void prep_kernel(const float* __restrict__ cls,
                            const float* __restrict__ w_qkv,
                            const float* __restrict__ b_qkv,
                            const float* __restrict__ w_out,
                            const float* __restrict__ b_out) {
    __shared__ float s_cls[EE];
    __shared__ float s_q0[EE];
    int tid = threadIdx.x;
    s_cls[tid] = cls[tid];
    __syncthreads();
    // q0[f] = W_q[f,:] . cls + b_q[f]
    float acc = b_qkv[tid];
    const float* wr = w_qkv + (size_t)tid * EE;
    #pragma unroll 8
    for (int e = 0; e < EE; e++) acc += wr[e] * s_cls[e];
    s_q0[tid] = acc;
    __syncthreads();

    const float scale = 0.125f;  // 1/sqrt(64)
    // u[h*EE+e] = scale * sum_d q0[h*DH+d] * W_k[h*DH+d, e]
    for (int k = 0; k < HH; k++) {
        int h = k, e = tid;
        float s = 0.f;
        #pragma unroll 8
        for (int d = 0; d < DH; d++)
            s += s_q0[h*DH + d] * w_qkv[(size_t)(EE + h*DH + d) * EE + e];
        g_u[h*EE + e] = s * scale;
    }
    if (tid < HH) {
        float s = 0.f;
        for (int d = 0; d < DH; d++)
            s += s_q0[tid*DH + d] * b_qkv[EE + tid*DH + d];
        g_cb[tid] = s * scale;
    }
    // bias2[f] = W_out[f,:] . b_v + b_out[f]
    float s2 = b_out[tid];
    const float* wo = w_out + (size_t)tid * EE;
    #pragma unroll 8
    for (int g = 0; g < EE; g++) s2 += wo[g] * b_qkv[2*EE + g];
    g_bias2[tid] = s2;
}

// ---------------- kernel 2: M2T = (W_out @ blockdiag(W_v))^T ----------------
__global__ void m2t_kernel(const float* __restrict__ w_qkv,
                           const float* __restrict__ w_out) {
    __shared__ float s_wo[EE];
    int f = blockIdx.x, tid = threadIdx.x;
    s_wo[tid] = w_out[(size_t)f * EE + tid];
    __syncthreads();
    #pragma unroll
    for (int k = 0; k < HH; k++) {
        int h = k, e = tid;        // j = h*EE + e
        float s = 0.f;
        #pragma unroll 8
        for (int d = 0; d < DH; d++)
            s += s_wo[h*DH + d] * w_qkv[(size_t)(2*EE + h*DH + d) * EE + e];
        g_M2T[(size_t)(h*EE + e) * EE + f] = s;
    }
}

// ---------------- kernel 3: attention -> xbar (one CTA per (b,c)) ----------------
__global__ void attn_kernel(const float* __restrict__ x,
                            const int* __restrict__ real_rows,
                            const float* __restrict__ cls) {
    __shared__ __align__(16) float s_u[HH*EE];
    __shared__ __align__(16) float s_sc[HH][SS];
    __shared__ __align__(16) float s_cls[EE];
    __shared__ float s_cb[HH];

    int bc  = blockIdx.x;
    int b   = bc >> 5;            // C = 32
    int tid = threadIdx.x;
    int warp = tid >> 5, lane = tid & 31;

    for (int i = tid; i < HH*EE; i += 256) s_u[i] = g_u[i];
    s_cls[tid] = cls[tid];
    if (tid < HH) s_cb[tid] = g_cb[tid];
    __syncthreads();

    int nk = real_rows[b] + 1;    // valid key positions: 0..nk-1
    const float* xbase = x + (size_t)bc * RR * EE;

    // ---- phase A: scores[h][pos] = u[h] . row + cb[h] ----
    for (int pos = warp; pos < nk; pos += 8) {
        const float* row = (pos == 0) ? s_cls : (xbase + (size_t)(pos - 1) * EE);
        float4 v0 = *(const float4*)(row + lane*4);
        float4 v1 = *(const float4*)(row + 128 + lane*4);
        float acc[HH];
        #pragma unroll
        for (int h = 0; h < HH; h++) {
            float4 u0 = *(const float4*)(s_u + h*EE + lane*4);
            float4 u1 = *(const float4*)(s_u + h*EE + 128 + lane*4);
            acc[h] = v0.x*u0.x + v0.y*u0.y + v0.z*u0.z + v0.w*u0.w
                   + v1.x*u1.x + v1.y*u1.y + v1.z*u1.z + v1.w*u1.w;
        }
        #pragma unroll
        for (int o = 16; o; o >>= 1) {
            #pragma unroll
            for (int h = 0; h < HH; h++)
                acc[h] += __shfl_xor_sync(0xffffffffu, acc[h], o);
        }
        if (lane == 0) {
            #pragma unroll
            for (int h = 0; h < HH; h++) s_sc[h][pos] = acc[h] + s_cb[h];
        }
    }
    __syncthreads();

    // ---- phase B: softmax over valid keys, per head (warp h) ----
    if (warp < HH) {
        int h = warp;
        float m = -3.0e38f;
        for (int p = lane; p < nk; p += 32) m = fmaxf(m, s_sc[h][p]);
        #pragma unroll
        for (int o = 16; o; o >>= 1) m = fmaxf(m, __shfl_xor_sync(0xffffffffu, m, o));
        float sum = 0.f;
        for (int p = lane; p < nk; p += 32) {
            float ev = __expf(s_sc[h][p] - m);
            s_sc[h][p] = ev;
            sum += ev;
        }
        #pragma unroll
        for (int o = 16; o; o >>= 1) sum += __shfl_xor_sync(0xffffffffu, sum, o);
        float inv = 1.f / sum;
        for (int p = lane; p < nk; p += 32) s_sc[h][p] *= inv;
    }
    __syncthreads();

    // ---- phase C: xbar[h][e] = sum_pos attn[h][pos] * row[e] ----
    float a0, a1, a2, a3;
    {
        float xv = s_cls[tid];
        a0 = s_sc[0][0]*xv; a1 = s_sc[1][0]*xv; a2 = s_sc[2][0]*xv; a3 = s_sc[3][0]*xv;
    }
    #pragma unroll 4
    for (int p = 1; p < nk; p++) {
        float xv = xbase[(size_t)(p - 1) * EE + tid];
        a0 += s_sc[0][p]*xv; a1 += s_sc[1][p]*xv;
        a2 += s_sc[2][p]*xv; a3 += s_sc[3][p]*xv;
    }
    float* xb = g_xbar + (size_t)bc * HID;
    xb[0*EE + tid] = a0; xb[1*EE + tid] = a1;
    xb[2*EE + tid] = a2; xb[3*EE + tid] = a3;
}

// ---------------- block-reduce helper ----------------
__device__ __forceinline__ float blk_sum(float v, float* s8, int tid) {
    #pragma unroll
    for (int o = 16; o; o >>= 1) v += __shfl_xor_sync(0xffffffffu, v, o);
    if ((tid & 31) == 0) s8[tid >> 5] = v;
    __syncthreads();
    float r = s8[0]+s8[1]+s8[2]+s8[3]+s8[4]+s8[5]+s8[6]+s8[7];
    __syncthreads();
    return r;
}

// ---------------- kernel 4: mha = M2 @ xbar + bias2, then LN. 4 tokens/CTA ----------------
#define TOK 4
__global__ void mha_ln_kernel(const float* __restrict__ ln_g,
                              const float* __restrict__ ln_b) {
    __shared__ __align__(16) float s_xb[TOK][HID];   // 16KB
    __shared__ float s_red[8];
    int t0 = blockIdx.x * TOK;
    int tid = threadIdx.x;

    for (int i = tid; i < TOK*HID; i += 256)
        s_xb[i >> 10][i & (HID-1)] = g_xbar[(size_t)t0 * HID + i];
    __syncthreads();

    float bias = g_bias2[tid];
    float acc[TOK] = {bias, bias, bias, bias};
    #pragma unroll 4
    for (int j = 0; j < HID; j++) {
        float m = g_M2T[(size_t)j * EE + tid];    // coalesced over f=tid
        #pragma unroll
        for (int tt = 0; tt < TOK; tt++) acc[tt] += m * s_xb[tt][j];
    }

    float g = ln_g[tid], bb = ln_b[tid];
    #pragma unroll
    for (int tt = 0; tt < TOK; tt++) {
        float sum = blk_sum(acc[tt], s_red, tid);
        float mu = sum * (1.f / EE);
        float d = acc[tt] - mu;
        float var = blk_sum(d*d, s_red, tid) * (1.f / EE);
        g_ln[(size_t)(t0 + tt) * EE + tid] = d * rsqrtf(var + LN_EPS) * g + bb;
    }
}

// ---------------- kernel 5: FFN + residual + column mask. 4 tokens/CTA ----------------
__global__ void ffn_kernel(const float* __restrict__ w1, const float* __restrict__ b1,
                           const float* __restrict__ w2, const float* __restrict__ b2,
                           const int* __restrict__ real_cols,
                           float* __restrict__ out) {
    __shared__ __align__(16) float s_ln[TOK][EE];     // 4KB
    __shared__ __align__(16) float s_hid[TOK][HID];   // 16KB
    int t0 = blockIdx.x * TOK;
    int tid = threadIdx.x;
    int warp = tid >> 5, lane = tid & 31;

    for (int i = tid; i < TOK*EE; i += 256)
        s_ln[i >> 8][i & (EE-1)] = g_ln[(size_t)t0 * EE + i];
    __syncthreads();

    // hidden[j] = relu(W1[j,:] . ln + b1[j]); warp handles j = warp, warp+8, ...
    for (int j = warp; j < HID; j += 8) {
        const float* w1r = w1 + (size_t)j * EE;
        float4 wv0 = ((const float4*)w1r)[lane];
        float4 wv1 = ((const float4*)w1r)[32 + lane];
        float acc[TOK];
        #pragma unroll
        for (int tt = 0; tt < TOK; tt++) {
            float4 l0 = *(const float4*)(s_ln[tt] + lane*4);
            float4 l1 = *(const float4*)(s_ln[tt] + 128 + lane*4);
            acc[tt] = wv0.x*l0.x + wv0.y*l0.y + wv0.z*l0.z + wv0.w*l0.w
                    + wv1.x*l1.x + wv1.y*l1.y + wv1.z*l1.z + wv1.w*l1.w;
        }
        #pragma unroll
        for (int o = 16; o; o >>= 1) {
            #pragma unroll
            for (int tt = 0; tt < TOK; tt++)
                acc[tt] += __shfl_xor_sync(0xffffffffu, acc[tt], o);
        }
        if (lane == 0) {
            float bj = b1[j];
            #pragma unroll
            for (int tt = 0; tt < TOK; tt++)
                s_hid[tt][j] = fmaxf(acc[tt] + bj, 0.f);
        }
    }
    __syncthreads();

    // out[f] = ln[f] + W2[f,:] . hidden + b2[f]; warp handles f = warp, warp+8, ...
    for (int f = warp; f < EE; f += 8) {
        const float* w2r = w2 + (size_t)f * HID;
        float acc[TOK] = {0.f, 0.f, 0.f, 0.f};
        #pragma unroll
        for (int k = 0; k < 8; k++) {
            float4 wv = ((const float4*)w2r)[k*32 + lane];
            #pragma unroll
            for (int tt = 0; tt < TOK; tt++) {
                float4 hv = *(const float4*)(s_hid[tt] + k*128 + lane*4);
                acc[tt] += wv.x*hv.x + wv.y*hv.y + wv.z*hv.z + wv.w*hv.w;
            }
        }
        #pragma unroll
        for (int o = 16; o; o >>= 1) {
            #pragma unroll
            for (int tt = 0; tt < TOK; tt++)
                acc[tt] += __shfl_xor_sync(0xffffffffu, acc[tt], o);
        }
        if (lane == 0) {
            float bf = b2[f];
            #pragma unroll
            for (int tt = 0; tt < TOK; tt++) {
                int t = t0 + tt;
                int bidx = t >> 5, cidx = t & 31;
                float val = (cidx < real_cols[bidx])
                          ? (s_ln[tt][f] + acc[tt] + bf) : 0.f;
                out[(size_t)t * EE + f] = val;
            }
        }
    }
}

// ---------------- launch ----------------
extern "C" void kernel_launch(void* const* d_in, const int* in_sizes, int n_in,
                              void* d_out, int out_size) {
    const float* x         = (const float*)d_in[0];
    const int*   real_cols = (const int*)  d_in[1];
    const int*   real_rows = (const int*)  d_in[2];
    const float* cls       = (const float*)d_in[3];
    const float* w_qkv     = (const float*)d_in[4];
    const float* b_qkv     = (const float*)d_in[5];
    const float* w_out     = (const float*)d_in[6];
    const float* b_out     = (const float*)d_in[7];
    const float* ln_g      = (const float*)d_in[8];
    const float* ln_b      = (const float*)d_in[9];
    const float* w1        = (const float*)d_in[10];
    const float* b1        = (const float*)d_in[11];
    const float* w2        = (const float*)d_in[12];
    const float* b2        = (const float*)d_in[13];
    float* out = (float*)d_out;

    prep_kernel  <<<1,   256>>>(cls, w_qkv, b_qkv, w_out, b_out);
    m2t_kernel   <<<EE,  256>>>(w_qkv, w_out);
    attn_kernel  <<<NBC, 256>>>(x, real_rows, cls);
    mha_ln_kernel<<<NBC/TOK, 256>>>(ln_g, ln_b);
    ffn_kernel   <<<NBC/TOK, 256>>>(w1, b1, w2, b2, real_cols, out);
}

// round 2
// speedup vs baseline: 1.9290x; 1.9290x over previous
#include <cuda_runtime.h>
#include <cuda_bf16.h>
#include <cstdint>

#define EE    256
#define HH    4
#define DH    64
#define BB    8
#define CC    32
#define RR    255
#define SS    256
#define HID   1024
#define NBC   (BB*CC)      // 256 (b,c) tokens
#define TOK   4
#define LN_EPS 1e-5f

// ---------------- device scratch ----------------
__device__ float g_u[HH*EE];
__device__ float g_cb[HH];
__device__ float g_bias2[EE];
__device__ float g_M2T[HID*EE];     // [j][f], j = h*EE+e
__device__ float g_W1T[EE*HID];     // [e][j]
__device__ float g_W2T[HID*EE];     // [j][f]
__device__ float g_xbar[NBC*HID];   // [t][j], j = h*EE+e
__device__ float g_ln[NBC*EE];
__device__ float g_hid[NBC*HID];
__device__ float g_part[4*NBC*EE];  // mha partials per j-slice
__device__ float g_part2[4*NBC*EE]; // ffn2 partials per j-slice

// ---------------- kernel: tiny precompute ----------------
__global__ void prep_kernel(const float* __restrict__ cls,
                            const float* __restrict__ w_qkv,
                            const float* __restrict__ b_qkv,
                            const float* __restrict__ w_out,
                            const float* __restrict__ b_out) {
    __shared__ float s_cls[EE];
    __shared__ float s_q0[EE];
    int tid = threadIdx.x;
    s_cls[tid] = cls[tid];
    __syncthreads();
    float acc = b_qkv[tid];
    const float* wr = w_qkv + (size_t)tid * EE;
    #pragma unroll 8
    for (int e = 0; e < EE; e++) acc += wr[e] * s_cls[e];
    s_q0[tid] = acc;
    __syncthreads();

    const float scale = 0.125f;
    for (int h = 0; h < HH; h++) {
        float s = 0.f;
        #pragma unroll 8
        for (int d = 0; d < DH; d++)
            s += s_q0[h*DH + d] * w_qkv[(size_t)(EE + h*DH + d) * EE + tid];
        g_u[h*EE + tid] = s * scale;
    }
    if (tid < HH) {
        float s = 0.f;
        for (int d = 0; d < DH; d++)
            s += s_q0[tid*DH + d] * b_qkv[EE + tid*DH + d];
        g_cb[tid] = s * scale;
    }
    float s2 = b_out[tid];
    const float* wo = w_out + (size_t)tid * EE;
    #pragma unroll 8
    for (int g = 0; g < EE; g++) s2 += wo[g] * b_qkv[2*EE + g];
    g_bias2[tid] = s2;
}

// ---------------- kernel: M2T[j][f] ----------------
__global__ void m2t_kernel(const float* __restrict__ w_qkv,
                           const float* __restrict__ w_out) {
    __shared__ float s_wo[EE];
    int f = blockIdx.x, tid = threadIdx.x;
    s_wo[tid] = w_out[(size_t)f * EE + tid];
    __syncthreads();
    #pragma unroll
    for (int h = 0; h < HH; h++) {
        float s = 0.f;
        #pragma unroll 8
        for (int d = 0; d < DH; d++)
            s += s_wo[h*DH + d] * w_qkv[(size_t)(2*EE + h*DH + d) * EE + tid];
        g_M2T[(size_t)(h*EE + tid) * EE + f] = s;
    }
}

// ---------------- kernel: tiled transpose ----------------
__global__ void transpose_kernel(const float* __restrict__ src,
                                 float* __restrict__ dst,
                                 int rows, int cols) {
    __shared__ float s[32][33];
    int bx = blockIdx.x * 32, by = blockIdx.y * 32;
    int tx = threadIdx.x, ty = threadIdx.y;
    s[ty][tx] = src[(size_t)(by + ty) * cols + bx + tx];
    __syncthreads();
    dst[(size_t)(bx + ty) * rows + by + tx] = s[tx][ty];
}

// ---------------- kernel: attention -> xbar ----------------
__global__ void attn_kernel(const float* __restrict__ x,
                            const int* __restrict__ real_rows,
                            const float* __restrict__ cls) {
    __shared__ __align__(16) float s_u[HH*EE];
    __shared__ __align__(16) float s_sc[HH][SS];
    __shared__ __align__(16) float s_cls[EE];
    __shared__ float s_cb[HH];

    int bc  = blockIdx.x;
    int b   = bc >> 5;
    int tid = threadIdx.x;
    int warp = tid >> 5, lane = tid & 31;

    for (int i = tid; i < HH*EE; i += 256) s_u[i] = g_u[i];
    s_cls[tid] = cls[tid];
    if (tid < HH) s_cb[tid] = g_cb[tid];
    __syncthreads();

    int nk = real_rows[b] + 1;
    const float* xbase = x + (size_t)bc * RR * EE;

    // scores
    for (int pos = warp; pos < nk; pos += 8) {
        const float* row = (pos == 0) ? s_cls : (xbase + (size_t)(pos - 1) * EE);
        float4 v0 = *(const float4*)(row + lane*4);
        float4 v1 = *(const float4*)(row + 128 + lane*4);
        float acc[HH];
        #pragma unroll
        for (int h = 0; h < HH; h++) {
            float4 u0 = *(const float4*)(s_u + h*EE + lane*4);
            float4 u1 = *(const float4*)(s_u + h*EE + 128 + lane*4);
            acc[h] = v0.x*u0.x + v0.y*u0.y + v0.z*u0.z + v0.w*u0.w
                   + v1.x*u1.x + v1.y*u1.y + v1.z*u1.z + v1.w*u1.w;
        }
        #pragma unroll
        for (int o = 16; o; o >>= 1) {
            #pragma unroll
            for (int h = 0; h < HH; h++)
                acc[h] += __shfl_xor_sync(0xffffffffu, acc[h], o);
        }
        if (lane == 0) {
            #pragma unroll
            for (int h = 0; h < HH; h++) s_sc[h][pos] = acc[h] + s_cb[h];
        }
    }
    __syncthreads();

    // softmax per head
    if (warp < HH) {
        int h = warp;
        float m = -3.0e38f;
        for (int p = lane; p < nk; p += 32) m = fmaxf(m, s_sc[h][p]);
        #pragma unroll
        for (int o = 16; o; o >>= 1) m = fmaxf(m, __shfl_xor_sync(0xffffffffu, m, o));
        float sum = 0.f;
        for (int p = lane; p < nk; p += 32) {
            float ev = __expf(s_sc[h][p] - m);
            s_sc[h][p] = ev;
            sum += ev;
        }
        #pragma unroll
        for (int o = 16; o; o >>= 1) sum += __shfl_xor_sync(0xffffffffu, sum, o);
        float inv = 1.f / sum;
        for (int p = lane; p < nk; p += 32) s_sc[h][p] *= inv;
    }
    __syncthreads();

    // weighted row sum
    float a0, a1, a2, a3;
    {
        float xv = s_cls[tid];
        a0 = s_sc[0][0]*xv; a1 = s_sc[1][0]*xv; a2 = s_sc[2][0]*xv; a3 = s_sc[3][0]*xv;
    }
    #pragma unroll 8
    for (int p = 1; p < nk; p++) {
        float xv = xbase[(size_t)(p - 1) * EE + tid];
        a0 += s_sc[0][p]*xv; a1 += s_sc[1][p]*xv;
        a2 += s_sc[2][p]*xv; a3 += s_sc[3][p]*xv;
    }
    float* xb = g_xbar + (size_t)bc * HID;
    xb[0*EE + tid] = a0; xb[1*EE + tid] = a1;
    xb[2*EE + tid] = a2; xb[3*EE + tid] = a3;
}

// ---------------- kernel: mha partial GEMM ----------------
// grid (64, 4): blockIdx.x = token group, blockIdx.y = j-slice (256 j each)
__global__ void mha_part_kernel() {
    __shared__ __align__(16) float s_xb[TOK][256];
    __shared__ __align__(16) float s_acc[4][TOK][EE];
    int t0 = blockIdx.x * TOK, slice = blockIdx.y;
    int tid = threadIdx.x;
    int fc = tid & 63, jg = tid >> 6;

    for (int i = tid; i < TOK*256; i += 256)
        s_xb[i >> 8][i & 255] = g_xbar[(size_t)(t0 + (i >> 8)) * HID + slice*256 + (i & 255)];
    __syncthreads();

    float4 a[TOK];
    #pragma unroll
    for (int tt = 0; tt < TOK; tt++) a[tt] = make_float4(0.f,0.f,0.f,0.f);

    const float4* Mp = ((const float4*)g_M2T) + (size_t)(slice*256 + jg*64) * 64 + fc;
    #pragma unroll 8
    for (int jl = 0; jl < 64; jl++) {
        float4 m = Mp[(size_t)jl * 64];
        int jj = jg*64 + jl;
        #pragma unroll
        for (int tt = 0; tt < TOK; tt++) {
            float xv = s_xb[tt][jj];
            a[tt].x += m.x*xv; a[tt].y += m.y*xv;
            a[tt].z += m.z*xv; a[tt].w += m.w*xv;
        }
    }
    #pragma unroll
    for (int tt = 0; tt < TOK; tt++)
        *(float4*)&s_acc[jg][tt][fc*4] = a[tt];
    __syncthreads();

    int f = tid;
    #pragma unroll
    for (int tt = 0; tt < TOK; tt++) {
        float s = s_acc[0][tt][f] + s_acc[1][tt][f] + s_acc[2][tt][f] + s_acc[3][tt][f];
        g_part[((size_t)slice * NBC + t0 + tt) * EE + f] = s;
    }
}

// ---------------- block-reduce helper ----------------
__device__ __forceinline__ float blk_sum(float v, float* s8, int tid) {
    #pragma unroll
    for (int o = 16; o; o >>= 1) v += __shfl_xor_sync(0xffffffffu, v, o);
    if ((tid & 31) == 0) s8[tid >> 5] = v;
    __syncthreads();
    float r = s8[0]+s8[1]+s8[2]+s8[3]+s8[4]+s8[5]+s8[6]+s8[7];
    __syncthreads();
    return r;
}

// ---------------- kernel: reduce partials + LayerNorm ----------------
__global__ void lnred_kernel(const float* __restrict__ ln_g,
                             const float* __restrict__ ln_b) {
    __shared__ float s_red[8];
    int t0 = blockIdx.x * TOK;
    int tid = threadIdx.x;
    float g = ln_g[tid], bb = ln_b[tid], bias = g_bias2[tid];
    #pragma unroll
    for (int tt = 0; tt < TOK; tt++) {
        int t = t0 + tt;
        float v = bias
                + g_part[((size_t)0*NBC + t)*EE + tid]
                + g_part[((size_t)1*NBC + t)*EE + tid]
                + g_part[((size_t)2*NBC + t)*EE + tid]
                + g_part[((size_t)3*NBC + t)*EE + tid];
        float mu = blk_sum(v, s_red, tid) * (1.f/EE);
        float d = v - mu;
        float var = blk_sum(d*d, s_red, tid) * (1.f/EE);
        g_ln[(size_t)t * EE + tid] = d * rsqrtf(var + LN_EPS) * g + bb;
    }
}

// ---------------- kernel: FFN hidden ----------------
// grid (64, 4): blockIdx.y = j-slice (256 j each); reduce over e split in-block
__global__ void ffn1_kernel(const float* __restrict__ b1) {
    __shared__ __align__(16) float s_ln[TOK][EE];
    __shared__ __align__(16) float s_acc[4][TOK][256];
    int t0 = blockIdx.x * TOK, slice = blockIdx.y;
    int tid = threadIdx.x;
    int jc = tid & 63, eg = tid >> 6;

    for (int i = tid; i < TOK*EE; i += 256)
        s_ln[i >> 8][i & 255] = g_ln[(size_t)(t0 + (i >> 8)) * EE + (i & 255)];
    __syncthreads();

    float4 a[TOK];
    #pragma unroll
    for (int tt = 0; tt < TOK; tt++) a[tt] = make_float4(0.f,0.f,0.f,0.f);

    // W1T row e has 1024 floats = 256 float4; j = slice*256 + jc*4
    const float4* Wp = ((const float4*)g_W1T) + (size_t)(eg*64) * 256 + slice*64 + jc;
    #pragma unroll 8
    for (int el = 0; el < 64; el++) {
        float4 w = Wp[(size_t)el * 256];
        int e = eg*64 + el;
        #pragma unroll
        for (int tt = 0; tt < TOK; tt++) {
            float lv = s_ln[tt][e];
            a[tt].x += w.x*lv; a[tt].y += w.y*lv;
            a[tt].z += w.z*lv; a[tt].w += w.w*lv;
        }
    }
    #pragma unroll
    for (int tt = 0; tt < TOK; tt++)
        *(float4*)&s_acc[eg][tt][jc*4] = a[tt];
    __syncthreads();

    float bj = b1[slice*256 + tid];
    #pragma unroll
    for (int tt = 0; tt < TOK; tt++) {
        float s = s_acc[0][tt][tid] + s_acc[1][tt][tid] + s_acc[2][tt][tid] + s_acc[3][tt][tid];
        g_hid[(size_t)(t0 + tt) * HID + slice*256 + tid] = fmaxf(s + bj, 0.f);
    }
}

// ---------------- kernel: FFN out partial GEMM ----------------
// grid (64, 4): blockIdx.y = j-slice of the 1024 reduction
__global__ void ffn2_kernel() {
    __shared__ __align__(16) float s_h[TOK][256];
    __shared__ __align__(16) float s_acc[4][TOK][EE];
    int t0 = blockIdx.x * TOK, slice = blockIdx.y;
    int tid = threadIdx.x;
    int fc = tid & 63, jg = tid >> 6;

    for (int i = tid; i < TOK*256; i += 256)
        s_h[i >> 8][i & 255] = g_hid[(size_t)(t0 + (i >> 8)) * HID + slice*256 + (i & 255)];
    __syncthreads();

    float4 a[TOK];
    #pragma unroll
    for (int tt = 0; tt < TOK; tt++) a[tt] = make_float4(0.f,0.f,0.f,0.f);

    const float4* Wp = ((const float4*)g_W2T) + (size_t)(slice*256 + jg*64) * 64 + fc;
    #pragma unroll 8
    for (int jl = 0; jl < 64; jl++) {
        float4 w = Wp[(size_t)jl * 64];
        int jj = jg*64 + jl;
        #pragma unroll
        for (int tt = 0; tt < TOK; tt++) {
            float hv = s_h[tt][jj];
            a[tt].x += w.x*hv; a[tt].y += w.y*hv;
            a[tt].z += w.z*hv; a[tt].w += w.w*hv;
        }
    }
    #pragma unroll
    for (int tt = 0; tt < TOK; tt++)
        *(float4*)&s_acc[jg][tt][fc*4] = a[tt];
    __syncthreads();

    int f = tid;
    #pragma unroll
    for (int tt = 0; tt < TOK; tt++) {
        float s = s_acc[0][tt][f] + s_acc[1][tt][f] + s_acc[2][tt][f] + s_acc[3][tt][f];
        g_part2[((size_t)slice * NBC + t0 + tt) * EE + f] = s;
    }
}

// ---------------- kernel: final reduce + residual + mask ----------------
__global__ void outred_kernel(const float* __restrict__ b2,
                              const int* __restrict__ real_cols,
                              float* __restrict__ out) {
    int t0 = blockIdx.x * TOK;
    int tid = threadIdx.x;
    float bf = b2[tid];
    #pragma unroll
    for (int tt = 0; tt < TOK; tt++) {
        int t = t0 + tt;
        int bidx = t >> 5, cidx = t & 31;
        float s = bf + g_ln[(size_t)t * EE + tid]
                + g_part2[((size_t)0*NBC + t)*EE + tid]
                + g_part2[((size_t)1*NBC + t)*EE + tid]
                + g_part2[((size_t)2*NBC + t)*EE + tid]
                + g_part2[((size_t)3*NBC + t)*EE + tid];
        out[(size_t)t * EE + tid] = (cidx < real_cols[bidx]) ? s : 0.f;
    }
}

// ---------------- launch ----------------
extern "C" void kernel_launch(void* const* d_in, const int* in_sizes, int n_in,
                              void* d_out, int out_size) {
    const float* x         = (const float*)d_in[0];
    const int*   real_cols = (const int*)  d_in[1];
    const int*   real_rows = (const int*)  d_in[2];
    const float* cls       = (const float*)d_in[3];
    const float* w_qkv     = (const float*)d_in[4];
    const float* b_qkv     = (const float*)d_in[5];
    const float* w_out     = (const float*)d_in[6];
    const float* b_out     = (const float*)d_in[7];
    const float* ln_g      = (const float*)d_in[8];
    const float* ln_b      = (const float*)d_in[9];
    const float* w1        = (const float*)d_in[10];
    const float* b1        = (const float*)d_in[11];
    const float* w2        = (const float*)d_in[12];
    const float* b2        = (const float*)d_in[13];
    float* out = (float*)d_out;

    float* gW1T; cudaGetSymbolAddress((void**)&gW1T, g_W1T);
    float* gW2T; cudaGetSymbolAddress((void**)&gW2T, g_W2T);

    prep_kernel<<<1, 256>>>(cls, w_qkv, b_qkv, w_out, b_out);
    m2t_kernel <<<EE, 256>>>(w_qkv, w_out);
    {   // W1 [1024][256] -> W1T [256][1024]
        dim3 g(EE/32, HID/32), b(32, 32);
        transpose_kernel<<<g, b>>>(w1, gW1T, HID, EE);
    }
    {   // W2 [256][1024] -> W2T [1024][256]
        dim3 g(HID/32, EE/32), b(32, 32);
        transpose_kernel<<<g, b>>>(w2, gW2T, EE, HID);
    }
    attn_kernel<<<NBC, 256>>>(x, real_rows, cls);
    mha_part_kernel<<<dim3(NBC/TOK, 4), 256>>>();
    lnred_kernel<<<NBC/TOK, 256>>>(ln_g, ln_b);
    ffn1_kernel<<<dim3(NBC/TOK, 4), 256>>>(b1);
    ffn2_kernel<<<dim3(NBC/TOK, 4), 256>>>();
    outred_kernel<<<NBC/TOK, 256>>>(b2, real_cols, out);
}

// round 3
// speedup vs baseline: 2.2323x; 1.1573x over previous
#include <cuda_runtime.h>
#include <cuda_bf16.h>
#include <cstdint>

#define EE    256
#define HH    4
#define DH    64
#define BB    8
#define CC    32
#define RR    255
#define SS    256
#define HID   1024
#define NBC   (BB*CC)      // 256 tokens
#define TOK   8
#define NSL   8            // j-split slices
#define LN_EPS 1e-5f

// ---------------- device scratch ----------------
__device__ float g_u[HH*EE];
__device__ float g_cb[HH];
__device__ float g_bias2[EE];
__device__ float g_M2T[HID*EE];      // [j][f]
__device__ float g_W1T[EE*HID];      // [e][j]
__device__ float g_W2T[HID*EE];      // [j][f]
__device__ float g_xbar[NBC*HID];    // [t][j]
__device__ float g_ln[NBC*EE];
__device__ float g_hid[NBC*HID];
__device__ float g_part[NSL*NBC*EE];
__device__ float g_part2[NSL*NBC*EE];

// ---------------- kernel: prep (block 256) + M2T (blocks 0..255) ----------------
__global__ void prep_kernel(const float* __restrict__ cls,
                            const float* __restrict__ w_qkv,
                            const float* __restrict__ b_qkv,
                            const float* __restrict__ w_out,
                            const float* __restrict__ b_out) {
    int tid = threadIdx.x;
    if (blockIdx.x < 256) {
        // M2T[j][f] = sum_d W_out[f, h*DH+d] * W_v[h*DH+d, e], j = h*EE+e
        __shared__ float s_wo[EE];
        int f = blockIdx.x;
        s_wo[tid] = w_out[(size_t)f * EE + tid];
        __syncthreads();
        #pragma unroll
        for (int h = 0; h < HH; h++) {
            float s = 0.f;
            #pragma unroll 8
            for (int d = 0; d < DH; d++)
                s += s_wo[h*DH + d] * w_qkv[(size_t)(2*EE + h*DH + d) * EE + tid];
            g_M2T[(size_t)(h*EE + tid) * EE + f] = s;
        }
        return;
    }
    // tiny precompute
    __shared__ float s_cls[EE];
    __shared__ float s_q0[EE];
    s_cls[tid] = cls[tid];
    __syncthreads();
    float acc = b_qkv[tid];
    const float* wr = w_qkv + (size_t)tid * EE;
    #pragma unroll 8
    for (int e = 0; e < EE; e++) acc += wr[e] * s_cls[e];
    s_q0[tid] = acc;
    __syncthreads();

    const float scale = 0.125f;
    for (int h = 0; h < HH; h++) {
        float s = 0.f;
        #pragma unroll 8
        for (int d = 0; d < DH; d++)
            s += s_q0[h*DH + d] * w_qkv[(size_t)(EE + h*DH + d) * EE + tid];
        g_u[h*EE + tid] = s * scale;
    }
    if (tid < HH) {
        float s = 0.f;
        for (int d = 0; d < DH; d++)
            s += s_q0[tid*DH + d] * b_qkv[EE + tid*DH + d];
        g_cb[tid] = s * scale;
    }
    float s2 = b_out[tid];
    const float* wo = w_out + (size_t)tid * EE;
    #pragma unroll 8
    for (int g = 0; g < EE; g++) s2 += wo[g] * b_qkv[2*EE + g];
    g_bias2[tid] = s2;
}

// ---------------- kernel: both weight transposes ----------------
__global__ void transpose2_kernel(const float* __restrict__ w1,
                                  const float* __restrict__ w2,
                                  float* __restrict__ w1t,
                                  float* __restrict__ w2t) {
    __shared__ float s[32][33];
    int bi = blockIdx.x;
    const float* src; float* dst; int rows, cols, bx, by;
    if (bi < 256) {          // W1 [1024][256] -> W1T [256][1024]
        src = w1; dst = w1t; rows = HID; cols = EE;
        bx = (bi & 7) * 32; by = (bi >> 3) * 32;
    } else {                 // W2 [256][1024] -> W2T [1024][256]
        bi -= 256;
        src = w2; dst = w2t; rows = EE; cols = HID;
        bx = (bi & 31) * 32; by = (bi >> 5) * 32;
    }
    int tx = threadIdx.x, ty = threadIdx.y;
    s[ty][tx] = src[(size_t)(by + ty) * cols + bx + tx];
    __syncthreads();
    dst[(size_t)(bx + ty) * rows + by + tx] = s[tx][ty];
}

// ---------------- kernel: attention -> xbar (1024 threads, 4-way pos split) ----------------
__global__ __launch_bounds__(1024) void attn_kernel(const float* __restrict__ x,
                            const int* __restrict__ real_rows,
                            const float* __restrict__ cls) {
    __shared__ __align__(16) float s_u[HH*EE];
    __shared__ __align__(16) float s_sc[HH][SS];
    __shared__ __align__(16) float s_cls[EE];
    __shared__ __align__(16) float s_part[4][HH][EE];   // 16KB
    __shared__ float s_cb[HH];

    int bc  = blockIdx.x;
    int b   = bc >> 5;
    int tid = threadIdx.x;
    int warp = tid >> 5, lane = tid & 31;

    s_u[tid] = g_u[tid];
    if (tid < EE) s_cls[tid] = cls[tid];
    if (tid < HH) s_cb[tid] = g_cb[tid];
    __syncthreads();

    int nk = real_rows[b] + 1;
    const float* xbase = x + (size_t)bc * RR * EE;

    // ---- phase A: scores, warp per position (32 warps) ----
    for (int pos = warp; pos < nk; pos += 32) {
        const float* row = (pos == 0) ? s_cls : (xbase + (size_t)(pos - 1) * EE);
        float4 v0 = *(const float4*)(row + lane*4);
        float4 v1 = *(const float4*)(row + 128 + lane*4);
        float acc[HH];
        #pragma unroll
        for (int h = 0; h < HH; h++) {
            float4 u0 = *(const float4*)(s_u + h*EE + lane*4);
            float4 u1 = *(const float4*)(s_u + h*EE + 128 + lane*4);
            acc[h] = v0.x*u0.x + v0.y*u0.y + v0.z*u0.z + v0.w*u0.w
                   + v1.x*u1.x + v1.y*u1.y + v1.z*u1.z + v1.w*u1.w;
        }
        #pragma unroll
        for (int o = 16; o; o >>= 1) {
            #pragma unroll
            for (int h = 0; h < HH; h++)
                acc[h] += __shfl_xor_sync(0xffffffffu, acc[h], o);
        }
        if (lane == 0) {
            #pragma unroll
            for (int h = 0; h < HH; h++) s_sc[h][pos] = acc[h] + s_cb[h];
        }
    }
    __syncthreads();

    // ---- phase B: softmax per head (warps 0..3) ----
    if (warp < HH) {
        int h = warp;
        float m = -3.0e38f;
        for (int p = lane; p < nk; p += 32) m = fmaxf(m, s_sc[h][p]);
        #pragma unroll
        for (int o = 16; o; o >>= 1) m = fmaxf(m, __shfl_xor_sync(0xffffffffu, m, o));
        float sum = 0.f;
        for (int p = lane; p < nk; p += 32) {
            float ev = __expf(s_sc[h][p] - m);
            s_sc[h][p] = ev;
            sum += ev;
        }
        #pragma unroll
        for (int o = 16; o; o >>= 1) sum += __shfl_xor_sync(0xffffffffu, sum, o);
        float inv = 1.f / sum;
        for (int p = lane; p < nk; p += 32) s_sc[h][p] *= inv;
    }
    __syncthreads();

    // ---- phase C: 4-way position split; pg = tid>>8, e = tid&255 ----
    int pg = tid >> 8, e = tid & 255;
    float a0 = 0.f, a1 = 0.f, a2 = 0.f, a3 = 0.f;
    #pragma unroll 8
    for (int pos = pg; pos < nk; pos += 4) {
        float xv = (pos == 0) ? s_cls[e] : xbase[(size_t)(pos - 1) * EE + e];
        a0 += s_sc[0][pos]*xv; a1 += s_sc[1][pos]*xv;
        a2 += s_sc[2][pos]*xv; a3 += s_sc[3][pos]*xv;
    }
    s_part[pg][0][e] = a0; s_part[pg][1][e] = a1;
    s_part[pg][2][e] = a2; s_part[pg][3][e] = a3;
    __syncthreads();

    // j = tid: h = tid>>8, e2 = tid&255
    int h = tid >> 8, e2 = tid & 255;
    g_xbar[(size_t)bc * HID + tid] =
        s_part[0][h][e2] + s_part[1][h][e2] + s_part[2][h][e2] + s_part[3][h][e2];
}

// ---------------- kernel: mha partial GEMM (grid 32x8, block 256) ----------------
__global__ void mha_part_kernel() {
    __shared__ __align__(16) float s_xb[TOK][128];       // 4KB
    __shared__ __align__(16) float s_acc[4][TOK][EE];    // 32KB
    int t0 = blockIdx.x * TOK, slice = blockIdx.y;
    int tid = threadIdx.x;
    int fc = tid & 63, jg = tid >> 6;

    for (int i = tid; i < TOK*128; i += 256)
        s_xb[i >> 7][i & 127] = g_xbar[(size_t)(t0 + (i >> 7)) * HID + slice*128 + (i & 127)];
    __syncthreads();

    float4 a[TOK];
    #pragma unroll
    for (int tt = 0; tt < TOK; tt++) a[tt] = make_float4(0.f,0.f,0.f,0.f);

    const float4* Mp = ((const float4*)g_M2T) + (size_t)(slice*128 + jg*32) * 64 + fc;
    #pragma unroll 8
    for (int jl = 0; jl < 32; jl++) {
        float4 m = Mp[(size_t)jl * 64];
        int jj = jg*32 + jl;
        #pragma unroll
        for (int tt = 0; tt < TOK; tt++) {
            float xv = s_xb[tt][jj];
            a[tt].x += m.x*xv; a[tt].y += m.y*xv;
            a[tt].z += m.z*xv; a[tt].w += m.w*xv;
        }
    }
    #pragma unroll
    for (int tt = 0; tt < TOK; tt++)
        *(float4*)&s_acc[jg][tt][fc*4] = a[tt];
    __syncthreads();

    int f = tid;
    #pragma unroll
    for (int tt = 0; tt < TOK; tt++) {
        float s = s_acc[0][tt][f] + s_acc[1][tt][f] + s_acc[2][tt][f] + s_acc[3][tt][f];
        g_part[((size_t)slice * NBC + t0 + tt) * EE + f] = s;
    }
}

// ---------------- kernel: LN reduce (warp per token; grid 64, block 128) ----------------
__global__ void lnred_kernel(const float* __restrict__ ln_g,
                             const float* __restrict__ ln_b) {
    int warp = threadIdx.x >> 5, lane = threadIdx.x & 31;
    int t = blockIdx.x * 4 + warp;
    float v[8];
    #pragma unroll
    for (int k = 0; k < 8; k++) {
        int f = k*32 + lane;
        float s = g_bias2[f];
        #pragma unroll
        for (int sl = 0; sl < NSL; sl++)
            s += g_part[((size_t)sl * NBC + t) * EE + f];
        v[k] = s;
    }
    float sum = v[0]+v[1]+v[2]+v[3]+v[4]+v[5]+v[6]+v[7];
    #pragma unroll
    for (int o = 16; o; o >>= 1) sum += __shfl_xor_sync(0xffffffffu, sum, o);
    float mu = sum * (1.f/EE);
    float vs = 0.f;
    #pragma unroll
    for (int k = 0; k < 8; k++) { float d = v[k] - mu; vs += d*d; }
    #pragma unroll
    for (int o = 16; o; o >>= 1) vs += __shfl_xor_sync(0xffffffffu, vs, o);
    float rs = rsqrtf(vs * (1.f/EE) + LN_EPS);
    #pragma unroll
    for (int k = 0; k < 8; k++) {
        int f = k*32 + lane;
        g_ln[(size_t)t * EE + f] = (v[k] - mu) * rs * ln_g[f] + ln_b[f];
    }
}

// ---------------- kernel: FFN hidden (grid 32x8, block 256) ----------------
__global__ void ffn1_kernel(const float* __restrict__ b1) {
    __shared__ __align__(16) float s_ln[TOK][EE];         // 8KB
    __shared__ __align__(16) float s_acc[8][TOK][128];    // 32KB
    int t0 = blockIdx.x * TOK, slice = blockIdx.y;
    int tid = threadIdx.x;
    int jc = tid & 31, eg = tid >> 5;

    for (int i = tid; i < TOK*EE; i += 256)
        s_ln[i >> 8][i & 255] = g_ln[(size_t)(t0 + (i >> 8)) * EE + (i & 255)];
    __syncthreads();

    float4 a[TOK];
    #pragma unroll
    for (int tt = 0; tt < TOK; tt++) a[tt] = make_float4(0.f,0.f,0.f,0.f);

    // W1T row e: 1024 floats = 256 float4; quad index = slice*32 + jc
    const float4* Wp = ((const float4*)g_W1T) + (size_t)(eg*32) * 256 + slice*32 + jc;
    #pragma unroll 8
    for (int el = 0; el < 32; el++) {
        float4 w = Wp[(size_t)el * 256];
        int e = eg*32 + el;
        #pragma unroll
        for (int tt = 0; tt < TOK; tt++) {
            float lv = s_ln[tt][e];
            a[tt].x += w.x*lv; a[tt].y += w.y*lv;
            a[tt].z += w.z*lv; a[tt].w += w.w*lv;
        }
    }
    #pragma unroll
    for (int tt = 0; tt < TOK; tt++)
        *(float4*)&s_acc[eg][tt][jc*4] = a[tt];
    __syncthreads();

    // write 128 j x TOK tokens: tt = tid>>7 gives 2 tokens per pass; iterate 4x
    #pragma unroll
    for (int r = 0; r < 4; r++) {
        int idx = r*256 + tid;           // 0..1023 over [tt][jj]
        int tt = idx >> 7, jj = idx & 127;
        float s = 0.f;
        #pragma unroll
        for (int eg2 = 0; eg2 < 8; eg2++) s += s_acc[eg2][tt][jj];
        g_hid[(size_t)(t0 + tt) * HID + slice*128 + jj] = fmaxf(s + b1[slice*128 + jj], 0.f);
    }
}

// ---------------- kernel: FFN out partial GEMM (grid 32x8, block 256) ----------------
__global__ void ffn2_kernel() {
    __shared__ __align__(16) float s_h[TOK][128];
    __shared__ __align__(16) float s_acc[4][TOK][EE];
    int t0 = blockIdx.x * TOK, slice = blockIdx.y;
    int tid = threadIdx.x;
    int fc = tid & 63, jg = tid >> 6;

    for (int i = tid; i < TOK*128; i += 256)
        s_h[i >> 7][i & 127] = g_hid[(size_t)(t0 + (i >> 7)) * HID + slice*128 + (i & 127)];
    __syncthreads();

    float4 a[TOK];
    #pragma unroll
    for (int tt = 0; tt < TOK; tt++) a[tt] = make_float4(0.f,0.f,0.f,0.f);

    const float4* Wp = ((const float4*)g_W2T) + (size_t)(slice*128 + jg*32) * 64 + fc;
    #pragma unroll 8
    for (int jl = 0; jl < 32; jl++) {
        float4 w = Wp[(size_t)jl * 64];
        int jj = jg*32 + jl;
        #pragma unroll
        for (int tt = 0; tt < TOK; tt++) {
            float hv = s_h[tt][jj];
            a[tt].x += w.x*hv; a[tt].y += w.y*hv;
            a[tt].z += w.z*hv; a[tt].w += w.w*hv;
        }
    }
    #pragma unroll
    for (int tt = 0; tt < TOK; tt++)
        *(float4*)&s_acc[jg][tt][fc*4] = a[tt];
    __syncthreads();

    int f = tid;
    #pragma unroll
    for (int tt = 0; tt < TOK; tt++) {
        float s = s_acc[0][tt][f] + s_acc[1][tt][f] + s_acc[2][tt][f] + s_acc[3][tt][f];
        g_part2[((size_t)slice * NBC + t0 + tt) * EE + f] = s;
    }
}

// ---------------- kernel: final reduce + residual + mask (warp per token) ----------------
__global__ void outred_kernel(const float* __restrict__ b2,
                              const int* __restrict__ real_cols,
                              float* __restrict__ out) {
    int warp = threadIdx.x >> 5, lane = threadIdx.x & 31;
    int t = blockIdx.x * 4 + warp;
    int bidx = t >> 5, cidx = t & 31;
    bool valid = cidx < real_cols[bidx];
    #pragma unroll
    for (int k = 0; k < 8; k++) {
        int f = k*32 + lane;
        float s = b2[f] + g_ln[(size_t)t * EE + f];
        #pragma unroll
        for (int sl = 0; sl < NSL; sl++)
            s += g_part2[((size_t)sl * NBC + t) * EE + f];
        out[(size_t)t * EE + f] = valid ? s : 0.f;
    }
}

// ---------------- launch ----------------
extern "C" void kernel_launch(void* const* d_in, const int* in_sizes, int n_in,
                              void* d_out, int out_size) {
    const float* x         = (const float*)d_in[0];
    const int*   real_cols = (const int*)  d_in[1];
    const int*   real_rows = (const int*)  d_in[2];
    const float* cls       = (const float*)d_in[3];
    const float* w_qkv     = (const float*)d_in[4];
    const float* b_qkv     = (const float*)d_in[5];
    const float* w_out     = (const float*)d_in[6];
    const float* b_out     = (const float*)d_in[7];
    const float* ln_g      = (const float*)d_in[8];
    const float* ln_b      = (const float*)d_in[9];
    const float* w1        = (const float*)d_in[10];
    const float* b1        = (const float*)d_in[11];
    const float* w2        = (const float*)d_in[12];
    const float* b2        = (const float*)d_in[13];
    float* out = (float*)d_out;

    float* gW1T; cudaGetSymbolAddress((void**)&gW1T, g_W1T);
    float* gW2T; cudaGetSymbolAddress((void**)&gW2T, g_W2T);

    prep_kernel<<<257, 256>>>(cls, w_qkv, b_qkv, w_out, b_out);
    transpose2_kernel<<<512, dim3(32,32)>>>(w1, w2, gW1T, gW2T);
    attn_kernel<<<NBC, 1024>>>(x, real_rows, cls);
    mha_part_kernel<<<dim3(NBC/TOK, NSL), 256>>>();
    lnred_kernel<<<NBC/4, 128>>>(ln_g, ln_b);
    ffn1_kernel<<<dim3(NBC/TOK, NSL), 256>>>(b1);
    ffn2_kernel<<<dim3(NBC/TOK, NSL), 256>>>();
    outred_kernel<<<NBC/4, 128>>>(b2, real_cols, out);
}

// round 4
// speedup vs baseline: 2.2693x; 1.0166x over previous
#include <cuda_runtime.h>
#include <cuda_bf16.h>
#include <cstdint>

#define EE    256
#define HH    4
#define DH    64
#define BB    8
#define CC    32
#define RR    255
#define SS    256
#define HID   1024
#define NBC   (BB*CC)      // 256 tokens
#define TOK   8
#define NSL   8            // j-split slices
#define LN_EPS 1e-5f

// ---------------- device scratch ----------------
__device__ float g_u[HH*EE];
__device__ float g_cb[HH];
__device__ float g_bias2[EE];
__device__ float g_M2T[HID*EE];      // [j][f]
__device__ float g_W1T[EE*HID];      // [e][j]
__device__ float g_W2T[HID*EE];      // [j][f]
__device__ float g_xbar[NBC*HID];    // [t][j]
__device__ float g_ln[NBC*EE];
__device__ float g_hid[NBC*HID];
__device__ float g_part[NSL*NBC*EE];
__device__ float g_part2[NSL*NBC*EE];

// ---------------- kernel: setup (m2t tiles + prep + both transposes) ----------------
// blocks [0,64)   : M2T tiled GEMM (h, et, ft)
// block  64       : tiny precompute (u, cb, bias2)
// blocks [65,321) : W1 [1024][256] -> W1T [256][1024]
// blocks [321,577): W2 [256][1024] -> W2T [1024][256]
__global__ void setup_kernel(const float* __restrict__ cls,
                             const float* __restrict__ w_qkv,
                             const float* __restrict__ b_qkv,
                             const float* __restrict__ w_out,
                             const float* __restrict__ b_out,
                             const float* __restrict__ w1,
                             const float* __restrict__ w2) {
    int bi = blockIdx.x;
    int tid = threadIdx.x;

    if (bi < 64) {
        // ---- M2T[j][f] = sum_d W_v[d_g, e] * W_out[f, d_g],  j = h*256+e ----
        __shared__ float sa[64][64];    // [d][el]  (W_v slice)
        __shared__ float sb[64][65];    // [fl][d]  (W_out slice, padded)
        int h = bi >> 4, e0 = ((bi >> 2) & 3) * 64, f0 = (bi & 3) * 64;
        for (int i = tid; i < 4096; i += 256) {
            int d = i >> 6, el = i & 63;
            sa[d][el] = w_qkv[(size_t)(2*EE + h*64 + d) * EE + e0 + el];
        }
        for (int i = tid; i < 4096; i += 256) {
            int fl = i >> 6, d = i & 63;
            sb[fl][d] = w_out[(size_t)(f0 + fl) * EE + h*64 + d];
        }
        __syncthreads();
        int tx = tid & 15, ty = tid >> 4;
        float acc[4][4] = {};
        #pragma unroll 4
        for (int d = 0; d < 64; d++) {
            float av[4], bv[4];
            #pragma unroll
            for (int i = 0; i < 4; i++) av[i] = sa[d][ty*4 + i];
            #pragma unroll
            for (int i = 0; i < 4; i++) bv[i] = sb[tx*4 + i][d];
            #pragma unroll
            for (int i = 0; i < 4; i++)
                #pragma unroll
                for (int j = 0; j < 4; j++) acc[i][j] += av[i] * bv[j];
        }
        #pragma unroll
        for (int i = 0; i < 4; i++)
            *(float4*)&g_M2T[(size_t)(h*256 + e0 + ty*4 + i) * EE + f0 + tx*4] = *(float4*)acc[i];
        return;
    }
    if (bi == 64) {
        // ---- tiny precompute ----
        __shared__ float s_cls[EE];
        __shared__ float s_q0[EE];
        s_cls[tid] = cls[tid];
        __syncthreads();
        float acc = b_qkv[tid];
        const float* wr = w_qkv + (size_t)tid * EE;
        #pragma unroll 8
        for (int e = 0; e < EE; e++) acc += wr[e] * s_cls[e];
        s_q0[tid] = acc;
        __syncthreads();

        const float scale = 0.125f;
        for (int h = 0; h < HH; h++) {
            float s = 0.f;
            #pragma unroll 8
            for (int d = 0; d < DH; d++)
                s += s_q0[h*DH + d] * w_qkv[(size_t)(EE + h*DH + d) * EE + tid];
            g_u[h*EE + tid] = s * scale;
        }
        if (tid < HH) {
            float s = 0.f;
            for (int d = 0; d < DH; d++)
                s += s_q0[tid*DH + d] * b_qkv[EE + tid*DH + d];
            g_cb[tid] = s * scale;
        }
        float s2 = b_out[tid];
        const float* wo = w_out + (size_t)tid * EE;
        #pragma unroll 8
        for (int g = 0; g < EE; g++) s2 += wo[g] * b_qkv[2*EE + g];
        g_bias2[tid] = s2;
        return;
    }
    // ---- transposes: 32x32 tile, 256 threads (32x8, 4 row-rounds) ----
    __shared__ float s[32][33];
    const float* src; float* dst; int rows, cols, bx, by;
    if (bi < 321) {            // W1 -> W1T
        int ti = bi - 65;
        src = w1; dst = g_W1T; rows = HID; cols = EE;
        bx = (ti & 7) * 32; by = (ti >> 3) * 32;
    } else {                   // W2 -> W2T
        int ti = bi - 321;
        src = w2; dst = g_W2T; rows = EE; cols = HID;
        bx = (ti & 31) * 32; by = (ti >> 5) * 32;
    }
    int tx = tid & 31, ty = tid >> 5;
    #pragma unroll
    for (int r = 0; r < 4; r++)
        s[ty + r*8][tx] = src[(size_t)(by + ty + r*8) * cols + bx + tx];
    __syncthreads();
    #pragma unroll
    for (int r = 0; r < 4; r++)
        dst[(size_t)(bx + ty + r*8) * rows + by + tx] = s[tx][ty + r*8];
}

// ---------------- kernel: attention -> xbar (1024 threads) ----------------
__global__ __launch_bounds__(1024) void attn_kernel(const float* __restrict__ x,
                            const int* __restrict__ real_rows,
                            const float* __restrict__ cls) {
    __shared__ __align__(16) float s_u[HH*EE];
    __shared__ __align__(16) float s_sc[HH][SS];
    __shared__ __align__(16) float s_cls[EE];
    __shared__ __align__(16) float s_part[8][HH][EE];   // 32KB
    __shared__ float s_cb[HH];

    int bc  = blockIdx.x;
    int b   = bc >> 5;
    int tid = threadIdx.x;
    int warp = tid >> 5, lane = tid & 31;

    s_u[tid] = g_u[tid];
    if (tid < EE) s_cls[tid] = cls[tid];
    if (tid < HH) s_cb[tid] = g_cb[tid];
    __syncthreads();

    int nk = real_rows[b] + 1;
    const float* xbase = x + (size_t)bc * RR * EE;

    // ---- phase A: scores, warp per position ----
    for (int pos = warp; pos < nk; pos += 32) {
        const float* row = (pos == 0) ? s_cls : (xbase + (size_t)(pos - 1) * EE);
        float4 v0 = *(const float4*)(row + lane*4);
        float4 v1 = *(const float4*)(row + 128 + lane*4);
        float acc[HH];
        #pragma unroll
        for (int h = 0; h < HH; h++) {
            float4 u0 = *(const float4*)(s_u + h*EE + lane*4);
            float4 u1 = *(const float4*)(s_u + h*EE + 128 + lane*4);
            acc[h] = v0.x*u0.x + v0.y*u0.y + v0.z*u0.z + v0.w*u0.w
                   + v1.x*u1.x + v1.y*u1.y + v1.z*u1.z + v1.w*u1.w;
        }
        #pragma unroll
        for (int o = 16; o; o >>= 1) {
            #pragma unroll
            for (int h = 0; h < HH; h++)
                acc[h] += __shfl_xor_sync(0xffffffffu, acc[h], o);
        }
        if (lane == 0) {
            #pragma unroll
            for (int h = 0; h < HH; h++) s_sc[h][pos] = acc[h] + s_cb[h];
        }
    }
    __syncthreads();

    // ---- phase B: softmax per head ----
    if (warp < HH) {
        int h = warp;
        float m = -3.0e38f;
        for (int p = lane; p < nk; p += 32) m = fmaxf(m, s_sc[h][p]);
        #pragma unroll
        for (int o = 16; o; o >>= 1) m = fmaxf(m, __shfl_xor_sync(0xffffffffu, m, o));
        float sum = 0.f;
        for (int p = lane; p < nk; p += 32) {
            float ev = __expf(s_sc[h][p] - m);
            s_sc[h][p] = ev;
            sum += ev;
        }
        #pragma unroll
        for (int o = 16; o; o >>= 1) sum += __shfl_xor_sync(0xffffffffu, sum, o);
        float inv = 1.f / sum;
        for (int p = lane; p < nk; p += 32) s_sc[h][p] *= inv;
    }
    __syncthreads();

    // ---- phase C: 8-way position split, float2 loads ----
    int pg = tid >> 7, ec = tid & 127;      // e = ec*2, ec*2+1
    float2 a[HH];
    #pragma unroll
    for (int h = 0; h < HH; h++) a[h] = make_float2(0.f, 0.f);
    #pragma unroll 4
    for (int pos = pg; pos < nk; pos += 8) {
        float2 xv = (pos == 0) ? *(const float2*)(s_cls + ec*2)
                               : *(const float2*)(xbase + (size_t)(pos - 1) * EE + ec*2);
        #pragma unroll
        for (int h = 0; h < HH; h++) {
            float w = s_sc[h][pos];
            a[h].x += w * xv.x; a[h].y += w * xv.y;
        }
    }
    #pragma unroll
    for (int h = 0; h < HH; h++)
        *(float2*)&s_part[pg][h][ec*2] = a[h];
    __syncthreads();

    // final reduce over pg: j = tid, h = tid>>8, e = tid&255
    int h2 = tid >> 8, e2 = tid & 255;
    float s = 0.f;
    #pragma unroll
    for (int g = 0; g < 8; g++) s += s_part[g][h2][e2];
    g_xbar[(size_t)bc * HID + tid] = s;
}

// ---------------- kernel: mha partial GEMM ----------------
__global__ __launch_bounds__(256, 3) void mha_part_kernel() {
    __shared__ __align__(16) float s_xb[TOK][128];
    __shared__ __align__(16) float s_acc[4][TOK][EE];
    int t0 = blockIdx.x * TOK, slice = blockIdx.y;
    int tid = threadIdx.x;
    int fc = tid & 63, jg = tid >> 6;

    for (int i = tid; i < TOK*128; i += 256)
        s_xb[i >> 7][i & 127] = g_xbar[(size_t)(t0 + (i >> 7)) * HID + slice*128 + (i & 127)];
    __syncthreads();

    float4 a[TOK];
    #pragma unroll
    for (int tt = 0; tt < TOK; tt++) a[tt] = make_float4(0.f,0.f,0.f,0.f);

    const float4* Mp = ((const float4*)g_M2T) + (size_t)(slice*128 + jg*32) * 64 + fc;
    #pragma unroll 4
    for (int jl = 0; jl < 32; jl++) {
        float4 m = Mp[(size_t)jl * 64];
        int jj = jg*32 + jl;
        #pragma unroll
        for (int tt = 0; tt < TOK; tt++) {
            float xv = s_xb[tt][jj];
            a[tt].x += m.x*xv; a[tt].y += m.y*xv;
            a[tt].z += m.z*xv; a[tt].w += m.w*xv;
        }
    }
    #pragma unroll
    for (int tt = 0; tt < TOK; tt++)
        *(float4*)&s_acc[jg][tt][fc*4] = a[tt];
    __syncthreads();

    int f = tid;
    #pragma unroll
    for (int tt = 0; tt < TOK; tt++) {
        float s = s_acc[0][tt][f] + s_acc[1][tt][f] + s_acc[2][tt][f] + s_acc[3][tt][f];
        g_part[((size_t)slice * NBC + t0 + tt) * EE + f] = s;
    }
}

// ---------------- kernel: LN reduce (warp per token) ----------------
__global__ void lnred_kernel(const float* __restrict__ ln_g,
                             const float* __restrict__ ln_b) {
    int warp = threadIdx.x >> 5, lane = threadIdx.x & 31;
    int t = blockIdx.x * 4 + warp;
    float v[8];
    #pragma unroll
    for (int k = 0; k < 8; k++) {
        int f = k*32 + lane;
        float s = g_bias2[f];
        #pragma unroll
        for (int sl = 0; sl < NSL; sl++)
            s += g_part[((size_t)sl * NBC + t) * EE + f];
        v[k] = s;
    }
    float sum = v[0]+v[1]+v[2]+v[3]+v[4]+v[5]+v[6]+v[7];
    #pragma unroll
    for (int o = 16; o; o >>= 1) sum += __shfl_xor_sync(0xffffffffu, sum, o);
    float mu = sum * (1.f/EE);
    float vs = 0.f;
    #pragma unroll
    for (int k = 0; k < 8; k++) { float d = v[k] - mu; vs += d*d; }
    #pragma unroll
    for (int o = 16; o; o >>= 1) vs += __shfl_xor_sync(0xffffffffu, vs, o);
    float rs = rsqrtf(vs * (1.f/EE) + LN_EPS);
    #pragma unroll
    for (int k = 0; k < 8; k++) {
        int f = k*32 + lane;
        g_ln[(size_t)t * EE + f] = (v[k] - mu) * rs * ln_g[f] + ln_b[f];
    }
}

// ---------------- kernel: FFN hidden ----------------
__global__ __launch_bounds__(256, 3) void ffn1_kernel(const float* __restrict__ b1) {
    __shared__ __align__(16) float s_ln[TOK][EE];
    __shared__ __align__(16) float s_acc[8][TOK][128];
    int t0 = blockIdx.x * TOK, slice = blockIdx.y;
    int tid = threadIdx.x;
    int jc = tid & 31, eg = tid >> 5;

    for (int i = tid; i < TOK*EE; i += 256)
        s_ln[i >> 8][i & 255] = g_ln[(size_t)(t0 + (i >> 8)) * EE + (i & 255)];
    __syncthreads();

    float4 a[TOK];
    #pragma unroll
    for (int tt = 0; tt < TOK; tt++) a[tt] = make_float4(0.f,0.f,0.f,0.f);

    const float4* Wp = ((const float4*)g_W1T) + (size_t)(eg*32) * 256 + slice*32 + jc;
    #pragma unroll 4
    for (int el = 0; el < 32; el++) {
        float4 w = Wp[(size_t)el * 256];
        int e = eg*32 + el;
        #pragma unroll
        for (int tt = 0; tt < TOK; tt++) {
            float lv = s_ln[tt][e];
            a[tt].x += w.x*lv; a[tt].y += w.y*lv;
            a[tt].z += w.z*lv; a[tt].w += w.w*lv;
        }
    }
    #pragma unroll
    for (int tt = 0; tt < TOK; tt++)
        *(float4*)&s_acc[eg][tt][jc*4] = a[tt];
    __syncthreads();

    #pragma unroll
    for (int r = 0; r < 4; r++) {
        int idx = r*256 + tid;
        int tt = idx >> 7, jj = idx & 127;
        float s = 0.f;
        #pragma unroll
        for (int eg2 = 0; eg2 < 8; eg2++) s += s_acc[eg2][tt][jj];
        g_hid[(size_t)(t0 + tt) * HID + slice*128 + jj] = fmaxf(s + b1[slice*128 + jj], 0.f);
    }
}

// ---------------- kernel: FFN out partial GEMM ----------------
__global__ __launch_bounds__(256, 3) void ffn2_kernel() {
    __shared__ __align__(16) float s_h[TOK][128];
    __shared__ __align__(16) float s_acc[4][TOK][EE];
    int t0 = blockIdx.x * TOK, slice = blockIdx.y;
    int tid = threadIdx.x;
    int fc = tid & 63, jg = tid >> 6;

    for (int i = tid; i < TOK*128; i += 256)
        s_h[i >> 7][i & 127] = g_hid[(size_t)(t0 + (i >> 7)) * HID + slice*128 + (i & 127)];
    __syncthreads();

    float4 a[TOK];
    #pragma unroll
    for (int tt = 0; tt < TOK; tt++) a[tt] = make_float4(0.f,0.f,0.f,0.f);

    const float4* Wp = ((const float4*)g_W2T) + (size_t)(slice*128 + jg*32) * 64 + fc;
    #pragma unroll 4
    for (int jl = 0; jl < 32; jl++) {
        float4 w = Wp[(size_t)jl * 64];
        int jj = jg*32 + jl;
        #pragma unroll
        for (int tt = 0; tt < TOK; tt++) {
            float hv = s_h[tt][jj];
            a[tt].x += w.x*hv; a[tt].y += w.y*hv;
            a[tt].z += w.z*hv; a[tt].w += w.w*hv;
        }
    }
    #pragma unroll
    for (int tt = 0; tt < TOK; tt++)
        *(float4*)&s_acc[jg][tt][fc*4] = a[tt];
    __syncthreads();

    int f = tid;
    #pragma unroll
    for (int tt = 0; tt < TOK; tt++) {
        float s = s_acc[0][tt][f] + s_acc[1][tt][f] + s_acc[2][tt][f] + s_acc[3][tt][f];
        g_part2[((size_t)slice * NBC + t0 + tt) * EE + f] = s;
    }
}

// ---------------- kernel: final reduce + residual + mask ----------------
__global__ void outred_kernel(const float* __restrict__ b2,
                              const int* __restrict__ real_cols,
                              float* __restrict__ out) {
    int warp = threadIdx.x >> 5, lane = threadIdx.x & 31;
    int t = blockIdx.x * 4 + warp;
    int bidx = t >> 5, cidx = t & 31;
    bool valid = cidx < real_cols[bidx];
    #pragma unroll
    for (int k = 0; k < 8; k++) {
        int f = k*32 + lane;
        float s = b2[f] + g_ln[(size_t)t * EE + f];
        #pragma unroll
        for (int sl = 0; sl < NSL; sl++)
            s += g_part2[((size_t)sl * NBC + t) * EE + f];
        out[(size_t)t * EE + f] = valid ? s : 0.f;
    }
}

// ---------------- launch ----------------
extern "C" void kernel_launch(void* const* d_in, const int* in_sizes, int n_in,
                              void* d_out, int out_size) {
    const float* x         = (const float*)d_in[0];
    const int*   real_cols = (const int*)  d_in[1];
    const int*   real_rows = (const int*)  d_in[2];
    const float* cls       = (const float*)d_in[3];
    const float* w_qkv     = (const float*)d_in[4];
    const float* b_qkv     = (const float*)d_in[5];
    const float* w_out     = (const float*)d_in[6];
    const float* b_out     = (const float*)d_in[7];
    const float* ln_g      = (const float*)d_in[8];
    const float* ln_b      = (const float*)d_in[9];
    const float* w1        = (const float*)d_in[10];
    const float* b1        = (const float*)d_in[11];
    const float* w2        = (const float*)d_in[12];
    const float* b2        = (const float*)d_in[13];
    float* out = (float*)d_out;

    setup_kernel<<<577, 256>>>(cls, w_qkv, b_qkv, w_out, b_out, w1, w2);
    attn_kernel<<<NBC, 1024>>>(x, real_rows, cls);
    mha_part_kernel<<<dim3(NBC/TOK, NSL), 256>>>();
    lnred_kernel<<<NBC/4, 128>>>(ln_g, ln_b);
    ffn1_kernel<<<dim3(NBC/TOK, NSL), 256>>>(b1);
    ffn2_kernel<<<dim3(NBC/TOK, NSL), 256>>>();
    outred_kernel<<<NBC/4, 128>>>(b2, real_cols, out);
}